// round 5
// baseline (speedup 1.0000x reference)
#include <cuda_runtime.h>
#include <cuda_bf16.h>
#include <cuda_fp16.h>
#include <math.h>
#include <stdint.h>

#define BATCH   1024
#define NTOK    64
#define DIM     512
#define HEADS   16
#define HDIM    32
#define NW      64
#define ROWS    (BATCH * NTOK)      // 65536
#define QKVCOLS (3 * DIM)           // 1536

// ---------------- device scratch ----------------
__device__ __align__(16) float  g_qkv[(size_t)ROWS * QKVCOLS];
__device__ __align__(16) __half g_xh[(size_t)ROWS * DIM];
__device__ __align__(16) __half g_xl[(size_t)ROWS * DIM];
__device__ __align__(16) __half g_wh[(size_t)QKVCOLS * DIM];
__device__ __align__(16) __half g_wl[(size_t)QKVCOLS * DIM];
__device__ __align__(16) __half g_ph[(size_t)DIM * DIM];
__device__ __align__(16) __half g_pl[(size_t)DIM * DIM];   // unused (1-term proj)
__device__ __align__(16) __half g_aoh[(size_t)ROWS * DIM];
__device__ float g_bias_table[225 * HEADS];
__device__ float g_rel_bias[HEADS * NTOK * NTOK];
__device__ float g_scale[HEADS];

// ---------------- helpers ----------------
__device__ __forceinline__ uint32_t smem_u32(const void* p) {
    uint32_t a;
    asm("{ .reg .u64 t; cvta.to.shared.u64 t, %1; cvt.u32.u64 %0, t; }" : "=r"(a) : "l"(p));
    return a;
}

#define LDSM4(r0,r1,r2,r3, addr) \
    asm volatile("ldmatrix.sync.aligned.m8n8.x4.shared.b16 {%0,%1,%2,%3}, [%4];" \
        : "=r"(r0),"=r"(r1),"=r"(r2),"=r"(r3) : "r"(addr))

#define MMA_F16(d, a, b) \
    asm volatile("mma.sync.aligned.m16n8k16.row.col.f32.f16.f16.f32 " \
        "{%0,%1,%2,%3}, {%4,%5,%6,%7}, {%8,%9}, {%0,%1,%2,%3};" \
        : "+f"(d[0]),"+f"(d[1]),"+f"(d[2]),"+f"(d[3]) \
        : "r"(a[0]),"r"(a[1]),"r"(a[2]),"r"(a[3]),"r"(b[0]),"r"(b[1]))

#define CP16(dst, src) \
    asm volatile("cp.async.ca.shared.global [%0], [%1], 16;" :: "r"(dst), "l"(src))
#define CP_COMMIT() asm volatile("cp.async.commit_group;" ::: "memory")
#define CP_WAIT1()  asm volatile("cp.async.wait_group 1;" ::: "memory")

// ---------------- fp32 -> fp16 hi/lo split ----------------
__global__ void split_f16(const float* __restrict__ in,
                          __half* __restrict__ hi,
                          __half* __restrict__ lo, int n4)
{
    int i = blockIdx.x * blockDim.x + threadIdx.x;
    if (i >= n4) return;
    float4 v = ((const float4*)in)[i];
    __half h[4], l[4];
    float x[4] = {v.x, v.y, v.z, v.w};
    #pragma unroll
    for (int j = 0; j < 4; j++) {
        h[j] = __float2half(x[j]);
        l[j] = __float2half(x[j] - __half2float(h[j]));
    }
    ((uint2*)hi)[i] = *(uint2*)h;
    ((uint2*)lo)[i] = *(uint2*)l;
}

// ---------------- CPB MLP ----------------
__global__ void cpb_mlp_kernel(const float* __restrict__ tbl,
                               const float* __restrict__ w1,
                               const float* __restrict__ b1,
                               const float* __restrict__ w2)
{
    int i = blockIdx.x, j = threadIdx.x;
    __shared__ float hid[512];
    float hv = tbl[i*2+0] * w1[j*2+0] + tbl[i*2+1] * w1[j*2+1] + b1[j];
    hid[j] = fmaxf(hv, 0.0f);
    __syncthreads();
    int warp = j >> 5, lane = j & 31;
    float s = 0.0f;
    #pragma unroll
    for (int c = lane; c < 512; c += 32) s += hid[c] * w2[warp*512 + c];
    #pragma unroll
    for (int off = 16; off > 0; off >>= 1) s += __shfl_xor_sync(0xffffffffu, s, off);
    if (lane == 0) g_bias_table[i*HEADS + warp] = s;
}

__global__ void cpb_expand_kernel(const int* __restrict__ idx,
                                  const float* __restrict__ logit_scale)
{
    int g = blockIdx.x * 256 + threadIdx.x;
    int h = g >> 12, nm = g & 4095;
    float v = g_bias_table[idx[nm]*HEADS + h];
    g_rel_bias[g] = 16.0f / (1.0f + expf(-v));
    if (g < HEADS) g_scale[g] = expf(fminf(logit_scale[g], 4.60517018598809136804f));
}

// ---------------------------------------------------------------------------
// split-fp16 GEMM (NT layout): C[M,*] = (A)(B)^T + bias, K=512.
// BM=128 BN=64 BK=32. 256 thr = 8 warps (4m x 2n), warp 32x32.
// 3-stage cp.async pipeline; smem rows padded to 80B (conflict-free LDSM).
// NTERMS=3: A=Ah+Al, B=Bh+Bl (hh+hl+lh). NTERMS=1: hi only.
// MODE 0: qk bias (q|0), 1: proj bias, 2: v bias. For MODE 1/2 col is local.
// ---------------------------------------------------------------------------
#define A_B 10240
#define B_B 5120

template <int MODE, int NTERMS>
__global__ __launch_bounds__(256, 2) void gemm_f16split(
    const __half* __restrict__ Ah, const __half* __restrict__ Al,
    const __half* __restrict__ Bh, const __half* __restrict__ Bl,
    const float* __restrict__ bias0,
    float* __restrict__ C, int N)
{
    constexpr int STG    = (NTERMS == 3) ? (2*A_B + 2*B_B) : (A_B + B_B);
    constexpr int OFF_AL = A_B;                                  // NTERMS==3 only
    constexpr int OFF_BH = (NTERMS == 3) ? 2*A_B : A_B;
    constexpr int OFF_BL = OFF_BH + B_B;                         // NTERMS==3 only

    extern __shared__ char smem[];

    const int tid  = threadIdx.x;
    const int bm   = blockIdx.y * 128;
    const int bn   = blockIdx.x * 64;
    const int wid  = tid >> 5, lane = tid & 31;
    const int wm   = (wid & 3) * 32;
    const int wn   = (wid >> 2) * 32;

    const uint32_t sbase = smem_u32(smem);

    float acc[2][4][4];
    #pragma unroll
    for (int a = 0; a < 2; a++)
        #pragma unroll
        for (int b = 0; b < 4; b++)
            #pragma unroll
            for (int c = 0; c < 4; c++) acc[a][b][c] = 0.0f;

    const int lrow = tid >> 2;       // 0..63
    const int lq   = tid & 3;        // 0..3
    auto load_stage = [&](int kt, int buf) {
        const uint32_t sb = sbase + buf * STG;
        const int k0 = kt * 32;
        #pragma unroll
        for (int i = 0; i < 2; i++) {
            int row = lrow + i * 64;
            uint32_t d = sb + (uint32_t)(row * 80 + lq * 16);
            const char* sh = (const char*)Ah + ((size_t)(bm + row) * 512 + k0 + lq * 8) * 2;
            CP16(d, sh);
            if (NTERMS == 3) {
                const char* sl = (const char*)Al + ((size_t)(bm + row) * 512 + k0 + lq * 8) * 2;
                CP16(d + OFF_AL, sl);
            }
        }
        {
            uint32_t d = sb + OFF_BH + (uint32_t)(lrow * 80 + lq * 16);
            const char* sh = (const char*)Bh + ((size_t)(bn + lrow) * 512 + k0 + lq * 8) * 2;
            CP16(d, sh);
            if (NTERMS == 3) {
                const char* sl = (const char*)Bl + ((size_t)(bn + lrow) * 512 + k0 + lq * 8) * 2;
                CP16(d + (OFF_BL - OFF_BH), sl);
            }
        }
        CP_COMMIT();
    };

    load_stage(0, 0);
    load_stage(1, 1);

    for (int kt = 0; kt < 16; kt++) {
        const int buf = kt % 3;
        CP_WAIT1();
        __syncthreads();

        if (kt + 2 < 16) load_stage(kt + 2, (kt + 2) % 3);
        else CP_COMMIT();

        const uint32_t sb  = sbase + buf * STG;
        const uint32_t aAh = sb;
        const uint32_t aAl = sb + OFF_AL;
        const uint32_t aBh = sb + OFF_BH;
        const uint32_t aBl = sb + OFF_BL;

        #pragma unroll
        for (int ks = 0; ks < 2; ks++) {
            const int kb = ks * 16;
            uint32_t ah[2][4], al[2][4], bh[4][2], bl[4][2];
            #pragma unroll
            for (int mt = 0; mt < 2; mt++) {
                int row = wm + mt*16 + (lane & 15);
                int col = kb + (lane >> 4) * 8;
                uint32_t off = (uint32_t)(row*40 + col) * 2;
                LDSM4(ah[mt][0], ah[mt][1], ah[mt][2], ah[mt][3], aAh + off);
                if (NTERMS == 3)
                    LDSM4(al[mt][0], al[mt][1], al[mt][2], al[mt][3], aAl + off);
            }
            #pragma unroll
            for (int np = 0; np < 2; np++) {
                int g = lane >> 3;
                int row = wn + np*16 + (lane & 7) + ((g >> 1) & 1) * 8;
                int col = kb + (g & 1) * 8;
                uint32_t off = (uint32_t)(row*40 + col) * 2;
                LDSM4(bh[2*np][0], bh[2*np][1], bh[2*np+1][0], bh[2*np+1][1], aBh + off);
                if (NTERMS == 3)
                    LDSM4(bl[2*np][0], bl[2*np][1], bl[2*np+1][0], bl[2*np+1][1], aBl + off);
            }
            #pragma unroll
            for (int mt = 0; mt < 2; mt++)
                #pragma unroll
                for (int nt = 0; nt < 4; nt++) {
                    MMA_F16(acc[mt][nt], ah[mt], bh[nt]);
                    if (NTERMS == 3) {
                        MMA_F16(acc[mt][nt], ah[mt], bl[nt]);
                        MMA_F16(acc[mt][nt], al[mt], bh[nt]);
                    }
                }
        }
        __syncthreads();
    }

    // ---- epilogue ----
    #pragma unroll
    for (int mt = 0; mt < 2; mt++) {
        #pragma unroll
        for (int nt = 0; nt < 4; nt++) {
            int row = bm + wm + mt*16 + (lane >> 2);
            int col = bn + wn + nt*8 + (lane & 3)*2;
            float b0, b1;
            if (MODE == 0) {        // qk: q_bias | zeros (col < 1024 always)
                b0 = (col   < 512) ? bias0[col]   : 0.0f;
                b1 = (col+1 < 512) ? bias0[col+1] : 0.0f;
            } else {                // proj / v: direct (local col)
                b0 = bias0[col]; b1 = bias0[col+1];
            }
            float* p0 = C + (size_t)row * N + col;
            float* p1 = C + (size_t)(row + 8) * N + col;
            p0[0] = acc[mt][nt][0] + b0;  p0[1] = acc[mt][nt][1] + b1;
            p1[0] = acc[mt][nt][2] + b0;  p1[1] = acc[mt][nt][3] + b1;
        }
    }
}

// ---------------------------------------------------------------------------
// Fused window attention per (b,h). Register-resident S + warp softmax.
// Writes attn output as fp16 (consumed by 1-term proj GEMM).
// ---------------------------------------------------------------------------
__global__ __launch_bounds__(256) void attn_kernel(const float* __restrict__ qkv,
                                                   const float* __restrict__ mask,
                                                   __half* __restrict__ aoh)
{
    const int b = blockIdx.x;
    const int h = blockIdx.y;
    const int w = b & (NW - 1);
    const int tid = threadIdx.x;
    const int wid = tid >> 5, lane = tid & 31;

    __shared__ float qs[32][64];
    __shared__ float ks[32][64];
    __shared__ float vs[64][32];
    __shared__ float Pt[64][68];
    __shared__ float qn[64], kn[64];

    const float* base = qkv + (size_t)b * NTOK * QKVCOLS + h * HDIM;
    for (int e = tid; e < NTOK * HDIM; e += 256) {
        int n = e >> 5, d = e & 31;
        const float* r = base + (size_t)n * QKVCOLS;
        qs[d][n] = r[d];
        ks[d][n] = r[512 + d];
        vs[n][d] = r[1024 + d];
    }
    __syncthreads();

    if (tid < 128) {
        int n = tid & 63;
        bool isq = tid < 64;
        float s = 0.0f;
        #pragma unroll
        for (int d = 0; d < 32; d++) {
            float x = isq ? qs[d][n] : ks[d][n];
            s = fmaf(x, x, s);
        }
        float inv = 1.0f / fmaxf(sqrtf(s), 1e-12f);
        if (isq) qn[n] = inv; else kn[n] = inv;
    }
    __syncthreads();

    float s0[8], s1[8];
    #pragma unroll
    for (int r = 0; r < 8; r++) { s0[r] = 0.0f; s1[r] = 0.0f; }
    #pragma unroll
    for (int d = 0; d < 32; d++) {
        float kv0 = ks[d][lane];
        float kv1 = ks[d][lane + 32];
        #pragma unroll
        for (int r = 0; r < 8; r++) {
            float qv = qs[d][wid*8 + r];
            s0[r] = fmaf(qv, kv0, s0[r]);
            s1[r] = fmaf(qv, kv1, s1[r]);
        }
    }

    const float scale = g_scale[h];
    const float kn0 = kn[lane], kn1 = kn[lane + 32];
    const float* rb = g_rel_bias + h * (NTOK * NTOK);
    const float* mk = mask + (size_t)w * (NTOK * NTOK);

    #pragma unroll
    for (int r = 0; r < 8; r++) {
        int n = wid*8 + r;
        float qsc = qn[n] * scale;
        int off = n*64 + lane;
        float x0 = s0[r]*qsc*kn0 + rb[off]      + mk[off];
        float x1 = s1[r]*qsc*kn1 + rb[off + 32] + mk[off + 32];
        float mx = fmaxf(x0, x1);
        #pragma unroll
        for (int o = 16; o > 0; o >>= 1)
            mx = fmaxf(mx, __shfl_xor_sync(0xffffffffu, mx, o));
        float e0 = __expf(x0 - mx);
        float e1 = __expf(x1 - mx);
        float sm = e0 + e1;
        #pragma unroll
        for (int o = 16; o > 0; o >>= 1)
            sm += __shfl_xor_sync(0xffffffffu, sm, o);
        float inv = 1.0f / sm;
        Pt[lane][n]      = e0 * inv;
        Pt[lane + 32][n] = e1 * inv;
    }
    __syncthreads();

    float o[8];
    #pragma unroll
    for (int r = 0; r < 8; r++) o[r] = 0.0f;
    #pragma unroll
    for (int m = 0; m < 64; m++) {
        float vm = vs[m][lane];
        float4 p0 = *(const float4*)&Pt[m][wid*8];
        float4 p1 = *(const float4*)&Pt[m][wid*8 + 4];
        o[0] = fmaf(p0.x, vm, o[0]);  o[1] = fmaf(p0.y, vm, o[1]);
        o[2] = fmaf(p0.z, vm, o[2]);  o[3] = fmaf(p0.w, vm, o[3]);
        o[4] = fmaf(p1.x, vm, o[4]);  o[5] = fmaf(p1.y, vm, o[5]);
        o[6] = fmaf(p1.z, vm, o[6]);  o[7] = fmaf(p1.w, vm, o[7]);
    }
    #pragma unroll
    for (int r = 0; r < 8; r++) {
        size_t oi = (size_t)(b*NTOK + wid*8 + r) * DIM + h*HDIM + lane;
        aoh[oi] = __float2half(o[r]);
    }
}

// ---------------------------------------------------------------------------
extern "C" void kernel_launch(void* const* d_in, const int* in_sizes, int n_in,
                              void* d_out, int out_size)
{
    const float* x           = (const float*)d_in[0];
    const float* mask        = (const float*)d_in[1];
    const float* qkv_w       = (const float*)d_in[2];
    const float* q_bias      = (const float*)d_in[3];
    const float* v_bias      = (const float*)d_in[4];
    const float* logit_scale = (const float*)d_in[5];
    const float* cpb_w1      = (const float*)d_in[6];
    const float* cpb_b1      = (const float*)d_in[7];
    const float* cpb_w2      = (const float*)d_in[8];
    const float* proj_w      = (const float*)d_in[9];
    const float* proj_b      = (const float*)d_in[10];
    const float* rel_table   = (const float*)d_in[11];
    const int*   rel_idx     = (const int*)d_in[12];
    float*       out         = (float*)d_out;

    float* qkv_ptr;
    __half *xh, *xl, *wh, *wl, *ph, *pl, *aoh;
    cudaGetSymbolAddress((void**)&qkv_ptr, g_qkv);
    cudaGetSymbolAddress((void**)&xh, g_xh);   cudaGetSymbolAddress((void**)&xl, g_xl);
    cudaGetSymbolAddress((void**)&wh, g_wh);   cudaGetSymbolAddress((void**)&wl, g_wl);
    cudaGetSymbolAddress((void**)&ph, g_ph);   cudaGetSymbolAddress((void**)&pl, g_pl);
    cudaGetSymbolAddress((void**)&aoh, g_aoh);

    constexpr int SMEM3 = 3 * (2*A_B + 2*B_B);   // 92160
    constexpr int SMEM1 = 3 * (A_B + B_B);       // 46080
    cudaFuncSetAttribute(gemm_f16split<0,3>, cudaFuncAttributeMaxDynamicSharedMemorySize, SMEM3);
    cudaFuncSetAttribute(gemm_f16split<2,1>, cudaFuncAttributeMaxDynamicSharedMemorySize, SMEM1);
    cudaFuncSetAttribute(gemm_f16split<1,1>, cudaFuncAttributeMaxDynamicSharedMemorySize, SMEM1);

    // splits
    {
        int n4 = ROWS * DIM / 4;
        split_f16<<<(n4 + 255)/256, 256>>>(x, xh, xl, n4);
        n4 = QKVCOLS * DIM / 4;
        split_f16<<<(n4 + 255)/256, 256>>>(qkv_w, wh, wl, n4);
        n4 = DIM * DIM / 4;
        split_f16<<<(n4 + 255)/256, 256>>>(proj_w, ph, pl, n4);
    }

    // CPB
    cpb_mlp_kernel<<<225, 512>>>(rel_table, cpb_w1, cpb_b1, cpb_w2);
    cpb_expand_kernel<<<256, 256>>>(rel_idx, logit_scale);

    // q,k GEMM (3-term): [65536,512] x [1024,512]^T -> cols 0..1023 of g_qkv
    gemm_f16split<0,3><<<dim3(1024/64, ROWS/128), 256, SMEM3>>>(
        xh, xl, wh, wl, q_bias, qkv_ptr, QKVCOLS);

    // v GEMM (1-term): [65536,512] x [512,512]^T -> cols 1024..1535 of g_qkv
    gemm_f16split<2,1><<<dim3(512/64, ROWS/128), 256, SMEM1>>>(
        xh, nullptr, wh + (size_t)1024 * 512, nullptr, v_bias,
        qkv_ptr + 1024, QKVCOLS);

    // attention (writes fp16)
    attn_kernel<<<dim3(BATCH, HEADS), 256>>>(qkv_ptr, mask, aoh);

    // proj GEMM (1-term): [65536,512] x [512,512]^T -> d_out fp32
    gemm_f16split<1,1><<<dim3(512/64, ROWS/128), 256, SMEM1>>>(
        aoh, nullptr, ph, nullptr, proj_b, out, DIM);
}